// round 17
// baseline (speedup 1.0000x reference)
#include <cuda_runtime.h>
#include <cstdint>

#define BB 1024
#define DD 512
#define HH 512
#define AA 18
#define TT 64

// scratch (device globals: no alloc allowed). Partial fc1 sums: d-half 0 / 1.
__device__ float g_hA[BB * HH];
__device__ float g_hB[BB * HH];

// packed fp32x2 helpers (sm_103a): fma.rn.f32x2 = 2 independent IEEE fp32
// FMAs per instruction (FFMA2 — only reachable via PTX, never from plain C++).
#define PACK2(out, lo, hi) \
    asm("mov.b64 %0, {%1, %2};" : "=l"(out) : "f"(lo), "f"(hi))
#define UNPACK2(lo, hi, in) \
    asm("mov.b64 {%0, %1}, %2;" : "=f"(lo), "=f"(hi) : "l"(in))
#define FMA_F32X2(d, a, b, c) \
    asm("fma.rn.f32x2 %0, %1, %2, %3;" : "=l"(d) : "l"(a), "l"(b), "l"(c))

// ---------------------------------------------------------------------------
// task list builder with runtime int64/int32 detection (data is int32 per
// R5/R6 evidence; detection kept as a guard). R14/R15 lesson: any cross-block
// sample split must partition by sample identity, never by list position.
// Here both kernels keep ALL samples of a task inside one (task, *) block
// family, so list order is harmless.
// ---------------------------------------------------------------------------
__device__ __forceinline__ int build_task_list(
    const unsigned int* __restrict__ raw, int t, int tid, int nthreads,
    int* s_idx, int* s_cnt)
{
    if (tid == 0) *s_cnt = 0;
    bool odd_zero = true;
    for (int i = tid; i < BB / 2; i += nthreads)
        odd_zero &= (raw[2 * i + 1] == 0u);
    const int is64 = __syncthreads_and(odd_zero);
    for (int b = tid; b < BB; b += nthreads) {
        const int tv = is64 ? (int)raw[2 * b] : (int)raw[b];
        if (tv == t) s_idx[atomicAdd(s_cnt, 1)] = b;
    }
    __syncthreads();
    return *s_cnt;
}

// ---------------------------------------------------------------------------
// fc1 partial: grid (T, 2 d-halves of 256). 128 threads; thread owns 4 h cols
// (block covers all H=512) x 16 sample rows. x pre-duplicated as (x,x) float2
// in smem so the inner loop is LDS.64 broadcast + 2 packs + 32 FMA2 per d.
// Accumulation order over d is ascending per column — bit-identical to the
// R15/R16 passing fc1. d-half 0 folds in bias; relu happens in fc2.
// ---------------------------------------------------------------------------
__global__ __launch_bounds__(128) void fc1_kernel(
    const float* __restrict__ xs,
    const unsigned int* __restrict__ task_raw,
    const float* __restrict__ w1,
    const float* __restrict__ b1,
    float* __restrict__ gA,
    float* __restrict__ gB)
{
    const int t = blockIdx.x;
    const int d0 = blockIdx.y * 256;
    const int tid = threadIdx.x;

    __shared__ __align__(16) float2 s_xx[16][256];   // (x,x) pairs, 32 KB
    __shared__ int s_idx[128];
    __shared__ int s_cnt;

    const int cnt = build_task_list(task_raw, t, tid, 128, s_idx, &s_cnt);
    if (cnt == 0) return;

    const float* wbase = w1 + (size_t)t * DD * HH + (size_t)d0 * HH + tid * 4;
    float4 bias = make_float4(0.f, 0.f, 0.f, 0.f);
    if (d0 == 0)
        bias = *(const float4*)(b1 + (size_t)t * HH + tid * 4);
    float* gout = (d0 == 0) ? gA : gB;

    for (int c0 = 0; c0 < cnt; c0 += 16) {
        const int m = min(16, cnt - c0);
        // stage x rows for this d-half, duplicated into (x,x) pairs
        #pragma unroll
        for (int r = 0; r < 16; r++) {
            float2 v = make_float2(0.0f, 0.0f);
            if (r < m)
                v = *(const float2*)(xs + (size_t)s_idx[c0 + r] * DD + d0 + tid * 2);
            s_xx[r][tid * 2]     = make_float2(v.x, v.x);
            s_xx[r][tid * 2 + 1] = make_float2(v.y, v.y);
        }
        __syncthreads();

        unsigned long long acc0[16], acc1[16];   // cols (4t,4t+1) / (4t+2,4t+3)
        #pragma unroll
        for (int r = 0; r < 16; r++) { acc0[r] = 0ull; acc1[r] = 0ull; }

        // 4-deep float4 weight prefetch (w streamed from DRAM once)
        float4 wreg[4];
        #pragma unroll
        for (int k = 0; k < 4; k++)
            wreg[k] = *(const float4*)(wbase + (size_t)k * HH);

        for (int d = 0; d < 256; d += 4) {
            float4 wc[4];
            #pragma unroll
            for (int k = 0; k < 4; k++) wc[k] = wreg[k];
            if (d + 4 < 256) {
                #pragma unroll
                for (int k = 0; k < 4; k++)
                    wreg[k] = *(const float4*)(wbase + (size_t)(d + 4 + k) * HH);
            }
            #pragma unroll
            for (int k = 0; k < 4; k++) {
                unsigned long long wp0, wp1;
                PACK2(wp0, wc[k].x, wc[k].y);
                PACK2(wp1, wc[k].z, wc[k].w);
                #pragma unroll
                for (int r = 0; r < 16; r++) {
                    const unsigned long long xx =
                        *(const unsigned long long*)&s_xx[r][d + k];
                    FMA_F32X2(acc0[r], xx, wp0, acc0[r]);
                    FMA_F32X2(acc1[r], xx, wp1, acc1[r]);
                }
            }
        }

        for (int r = 0; r < m; r++) {
            const int b = s_idx[c0 + r];
            float4 v;
            UNPACK2(v.x, v.y, acc0[r]);
            UNPACK2(v.z, v.w, acc1[r]);
            v.x += bias.x; v.y += bias.y; v.z += bias.z; v.w += bias.w;
            *(float4*)(gout + (size_t)b * HH + tid * 4) = v;
        }
        __syncthreads();
    }
}

// ---------------------------------------------------------------------------
// JAX Threefry-2x32, partitionable convention (verified R9):
// bits[i] = w0 ^ w1 of threefry2x32(k0=0, k1=1, x0=0, x1=i)
// ---------------------------------------------------------------------------
__device__ __forceinline__ uint32_t rotl32(uint32_t x, int r) {
    return (x << r) | (x >> (32 - r));
}

__device__ uint2 threefry2x32(uint32_t k0, uint32_t k1, uint32_t x0, uint32_t x1)
{
    const uint32_t ks0 = k0, ks1 = k1, ks2 = k0 ^ k1 ^ 0x1BD11BDAu;
    x0 += ks0; x1 += ks1;
    x0 += x1; x1 = rotl32(x1, 13); x1 ^= x0;
    x0 += x1; x1 = rotl32(x1, 15); x1 ^= x0;
    x0 += x1; x1 = rotl32(x1, 26); x1 ^= x0;
    x0 += x1; x1 = rotl32(x1,  6); x1 ^= x0;
    x0 += ks1; x1 += ks2 + 1u;
    x0 += x1; x1 = rotl32(x1, 17); x1 ^= x0;
    x0 += x1; x1 = rotl32(x1, 29); x1 ^= x0;
    x0 += x1; x1 = rotl32(x1, 16); x1 ^= x0;
    x0 += x1; x1 = rotl32(x1, 24); x1 ^= x0;
    x0 += ks2; x1 += ks0 + 2u;
    x0 += x1; x1 = rotl32(x1, 13); x1 ^= x0;
    x0 += x1; x1 = rotl32(x1, 15); x1 ^= x0;
    x0 += x1; x1 = rotl32(x1, 26); x1 ^= x0;
    x0 += x1; x1 = rotl32(x1,  6); x1 ^= x0;
    x0 += ks0; x1 += ks1 + 3u;
    x0 += x1; x1 = rotl32(x1, 17); x1 ^= x0;
    x0 += x1; x1 = rotl32(x1, 29); x1 ^= x0;
    x0 += x1; x1 = rotl32(x1, 16); x1 ^= x0;
    x0 += x1; x1 = rotl32(x1, 24); x1 ^= x0;
    x0 += ks1; x1 += ks2 + 4u;
    x0 += x1; x1 = rotl32(x1, 13); x1 ^= x0;
    x0 += x1; x1 = rotl32(x1, 15); x1 ^= x0;
    x0 += x1; x1 = rotl32(x1, 26); x1 ^= x0;
    x0 += x1; x1 = rotl32(x1,  6); x1 ^= x0;
    x0 += ks2; x1 += ks0 + 5u;
    return make_uint2(x0, x1);
}

__device__ __forceinline__ uint32_t jax_random_bits(uint32_t i)
{
    uint2 r = threefry2x32(0u, 1u, 0u, i);
    return r.x ^ r.y;
}

// ---------------------------------------------------------------------------
// fc2 + log_softmax + gumbel categorical + log_prob + entropy.
// grid (T), 512 threads (16 warps): w2[t] staged ONCE per task (R16 staged it
// 4x — that duplication at latency-starved BW was the whole 22us). One warp
// per sample, 16 in flight. Math identical to the R16 passing version.
// ---------------------------------------------------------------------------
__global__ __launch_bounds__(512) void fc2_kernel(
    const unsigned int* __restrict__ task_raw,
    const float* __restrict__ w2,
    const float* __restrict__ b2,
    const float* __restrict__ hA,
    const float* __restrict__ hB,
    float* __restrict__ out)
{
    const int t = blockIdx.x;
    const int tid = threadIdx.x;

    __shared__ __align__(16) float s_w[HH * AA];   // 36 KB
    __shared__ float s_b[AA];
    __shared__ int s_idx[128];
    __shared__ int s_cnt;

    // stage w2[t] as float4 (2304 float4 across 512 threads)
    const float4* w2t = (const float4*)(w2 + (size_t)t * HH * AA);
    float4* swv = (float4*)s_w;
    for (int i = tid; i < (HH * AA) / 4; i += 512)
        swv[i] = w2t[i];
    if (tid < AA) s_b[tid] = b2[t * AA + tid];
    const int cnt = build_task_list(task_raw, t, tid, 512, s_idx, &s_cnt);

    const int warp = tid >> 5;
    const int l = tid & 31;

    for (int s = warp; s < cnt; s += 16) {
        const int b = s_idx[s];
        float hreg[16];
        #pragma unroll
        for (int i = 0; i < 16; i++) {
            const size_t off = (size_t)b * HH + i * 32 + l;
            hreg[i] = fmaxf(hA[off] + hB[off], 0.0f);
        }

        // per-lane partials for all 18 actions (i ascending)
        float acc[AA];
        #pragma unroll
        for (int a = 0; a < AA; a++) acc[a] = 0.0f;
        #pragma unroll
        for (int i = 0; i < 16; i++) {
            const float x = hreg[i];
            const float* wr = &s_w[(i * 32 + l) * AA];
            #pragma unroll
            for (int a = 0; a < AA; a++)
                acc[a] = fmaf(x, wr[a], acc[a]);
        }
        // 18 interleaved butterfly reductions
        #pragma unroll
        for (int off = 16; off > 0; off >>= 1) {
            #pragma unroll
            for (int a = 0; a < AA; a++)
                acc[a] += __shfl_xor_sync(0xffffffffu, acc[a], off);
        }
        float logit = -INFINITY;
        #pragma unroll
        for (int a = 0; a < AA; a++)
            if (l == a) logit = acc[a] + s_b[a];

        // log_softmax
        float mx = logit;
        #pragma unroll
        for (int off = 16; off > 0; off >>= 1)
            mx = fmaxf(mx, __shfl_xor_sync(0xffffffffu, mx, off));
        float ex = (l < AA) ? expf(logit - mx) : 0.0f;
        float sum = ex;
        #pragma unroll
        for (int off = 16; off > 0; off >>= 1)
            sum += __shfl_xor_sync(0xffffffffu, sum, off);
        const float lse = mx + logf(sum);
        const float logp = logit - lse;

        // entropy
        float ent = (l < AA) ? (-expf(logp) * logp) : 0.0f;
        #pragma unroll
        for (int off = 16; off > 0; off >>= 1)
            ent += __shfl_xor_sync(0xffffffffu, ent, off);

        // gumbel noise (JAX partitionable threefry, XOR convention)
        float y = -INFINITY;
        if (l < AA) {
            const uint32_t bits = jax_random_bits((uint32_t)(b * AA + l));
            const float f = __uint_as_float((bits >> 9) | 0x3f800000u) - 1.0f;
            const float TINY = 1.17549435e-38f;
            const float u = fmaxf(TINY, f * (1.0f - TINY) + TINY);
            const float g = -logf(-logf(u));
            y = logit + g;
        }
        // argmax, first-index tiebreak
        int bi = l;
        #pragma unroll
        for (int off = 16; off > 0; off >>= 1) {
            const float oy = __shfl_xor_sync(0xffffffffu, y, off);
            const int ob = __shfl_xor_sync(0xffffffffu, bi, off);
            if (oy > y || (oy == y && ob < bi)) { y = oy; bi = ob; }
        }
        const float lp_action = __shfl_sync(0xffffffffu, logp, bi);

        if (l == 0) {
            out[b] = (float)bi;
            out[BB + b] = lp_action;
            out[2 * BB + b] = ent;
        }
    }
}

extern "C" void kernel_launch(void* const* d_in, const int* in_sizes, int n_in,
                              void* d_out, int out_size)
{
    // Map inputs by element count (all distinct) — immune to metadata ordering.
    const float* xs = nullptr;
    const unsigned int* task_raw = nullptr;
    const float* w1 = nullptr;
    const float* b1 = nullptr;
    const float* w2 = nullptr;
    const float* b2 = nullptr;
    for (int i = 0; i < n_in; i++) {
        switch (in_sizes[i]) {
            case BB * DD:        xs = (const float*)d_in[i]; break;
            case BB:             task_raw = (const unsigned int*)d_in[i]; break;
            case TT * DD * HH:   w1 = (const float*)d_in[i]; break;
            case TT * HH:        b1 = (const float*)d_in[i]; break;
            case TT * HH * AA:   w2 = (const float*)d_in[i]; break;
            case TT * AA:        b2 = (const float*)d_in[i]; break;
            default: break;
        }
    }
    float* out = (float*)d_out;

    float *hA, *hB;
    cudaGetSymbolAddress((void**)&hA, g_hA);
    cudaGetSymbolAddress((void**)&hB, g_hB);

    dim3 g1(TT, 2);
    fc1_kernel<<<g1, 128>>>(xs, task_raw, w1, b1, hA, hB);
    fc2_kernel<<<TT, 512>>>(task_raw, w2, b2, hA, hB, out);
}